// round 2
// baseline (speedup 1.0000x reference)
#include <cuda_runtime.h>
#include <math.h>

#define TT 4096
#define CC 512
#define BB 32
#define WW 2055          // DWT output length
#define PITCH 2056
#define NROWS (BB*CC)    // 16384

__constant__ float cDLO[16] = {
 -0.00011747678400228192f, 0.0006754494059985568f, -0.0003917403729959771f, -0.00487035299301066f,
  0.008746094047015655f,   0.013981027917015516f,  -0.04408825393106472f,   -0.01736930100202211f,
  0.128747426620186f,      0.00047248457399797254f,-0.2840155429624281f,    -0.015829105256023893f,
  0.5853546836548691f,     0.6756307362980128f,     0.3128715909144659f,     0.05441584224308161f };
__constant__ float cDHI[16] = {
 -0.05441584224308161f,    0.3128715909144659f,    -0.6756307362980128f,     0.5853546836548691f,
  0.015829105256023893f,  -0.2840155429624281f,    -0.00047248457399797254f, 0.128747426620186f,
  0.01736930100202211f,   -0.04408825393106472f,   -0.013981027917015516f,   0.008746094047015655f,
  0.00487035299301066f,   -0.0003917403729959771f, -0.0006754494059985568f, -0.00011747678400228192f };
__constant__ float cRLO[16] = {
  0.05441584224308161f,    0.3128715909144659f,     0.6756307362980128f,     0.5853546836548691f,
 -0.015829105256023893f,  -0.2840155429624281f,     0.00047248457399797254f, 0.128747426620186f,
 -0.01736930100202211f,   -0.04408825393106472f,    0.013981027917015516f,   0.008746094047015655f,
 -0.00487035299301066f,   -0.0003917403729959771f,  0.0006754494059985568f, -0.00011747678400228192f };
__constant__ float cRHI[16] = {
 -0.00011747678400228192f,-0.0006754494059985568f, -0.0003917403729959771f,  0.00487035299301066f,
  0.008746094047015655f,  -0.013981027917015516f,  -0.04408825393106472f,    0.01736930100202211f,
  0.128747426620186f,     -0.00047248457399797254f,-0.2840155429624281f,     0.015829105256023893f,
  0.5853546836548691f,    -0.6756307362980128f,     0.3128715909144659f,    -0.05441584224308161f };

__device__ float g_lo[(size_t)NROWS * PITCH];
__device__ float g_hi[(size_t)NROWS * PITCH];
__device__ float g_thr[NROWS];

// ---------------------------------------------------------------------------
// Kernel 1: DWT. Lane = channel; each thread holds a 30-wide register window
// of its channel's time series and produces 8 output-pairs. Global loads are
// coalesced over c; results staged in smem so g_lo/g_hi writes coalesce over i.
// ---------------------------------------------------------------------------
__global__ __launch_bounds__(256) void k_dwt(const float* __restrict__ x) {
    int i0 = blockIdx.x * 64;
    int c0 = blockIdx.y * 32;
    int b  = blockIdx.z;
    int tid = threadIdx.x, lane = tid & 31, wp = tid >> 5;

    __shared__ float sOut[2][64][33];     // [band][i_local][channel]

    int iw0 = i0 + wp * 8;
    int p0w = 2 * iw0 - 14;               // window covers p0w .. p0w+29
    const float* xb = x + (size_t)b * TT * CC + (c0 + lane);

    float xw[30];
    if (p0w >= 0 && p0w + 29 < TT) {
        #pragma unroll
        for (int m = 0; m < 30; m++)
            xw[m] = xb[(size_t)(p0w + m) * CC];
    } else {
        #pragma unroll
        for (int m = 0; m < 30; m++) {
            int p = p0w + m;
            int t = (p < 0) ? (-1 - p) : ((p >= TT) ? (2 * TT - 1 - p) : p);
            xw[m] = xb[(size_t)t * CC];
        }
    }

    #pragma unroll
    for (int s = 0; s < 8; s++) {
        float alo = 0.f, ahi = 0.f;
        #pragma unroll
        for (int d = 0; d < 16; d++) {
            float v = xw[2 * s + 15 - d];
            alo = fmaf(v, cDLO[d], alo);
            ahi = fmaf(v, cDHI[d], ahi);
        }
        sOut[0][wp * 8 + s][lane] = alo;
        sOut[1][wp * 8 + s][lane] = ahi;
    }
    __syncthreads();

    // coalesced writes: 8 warps x 4 channels, lanes over i
    #pragma unroll
    for (int r = 0; r < 4; r++) {
        int cc = wp * 4 + r;
        size_t rowoff = (size_t)(b * CC + c0 + cc) * PITCH;
        #pragma unroll
        for (int half = 0; half < 2; half++) {
            int il = lane + half * 32;
            int i = i0 + il;
            if (i < WW) {
                g_lo[rowoff + i] = sOut[0][il][cc];
                g_hi[rowoff + i] = sOut[1][il][cc];
            }
        }
    }
}

// ---------------------------------------------------------------------------
// Kernel 2: exact per-row quantile via 8-bit radix select on float bits.
// Warp-aggregated histogram atomics (__match_any_sync) + shfl-based scan.
// Sentinel 0xFFFFFFFF pads ragged tail (never selected: squares have top
// byte <= 0x7F, rank k < 2055 counts only real values below).
// ---------------------------------------------------------------------------
__global__ __launch_bounds__(256) void k_quant(const float* __restrict__ qp) {
    int row = blockIdx.x;
    const float* h = g_hi + (size_t)row * PITCH;
    int tid = threadIdx.x, lane = tid & 31, wp = tid >> 5;

    unsigned int vals[9];
    #pragma unroll
    for (int e = 0; e < 9; e++) {
        int idx = tid + e * 256;
        if (idx < WW) { float v = h[idx]; vals[e] = __float_as_uint(v * v); }
        else vals[e] = 0xFFFFFFFFu;
    }

    float q = qp[0];
    float pos = q * (float)(WW - 1);
    int k = (int)floorf(pos);
    if (k < 0) k = 0;
    if (k > WW - 2) k = WW - 2;
    float frac = pos - (float)k;

    __shared__ unsigned int hist[256];
    __shared__ unsigned int wsum[8];
    __shared__ int s_sel, s_r;

    unsigned int prefix = 0;
    int r = k;
    #pragma unroll
    for (int shift = 24; shift >= 0; shift -= 8) {
        hist[tid] = 0;
        __syncthreads();
        unsigned int maskhi = (shift == 24) ? 0u : (0xFFFFFFFFu << (shift + 8));
        #pragma unroll
        for (int e = 0; e < 9; e++) {
            unsigned int u = vals[e];
            bool act = ((u & maskhi) == prefix);
            unsigned int key = act ? ((u >> shift) & 255u) : (0x100u + lane);
            unsigned int grp = __match_any_sync(0xFFFFFFFFu, key);
            if (act) {
                int leader = __ffs(grp) - 1;
                if (lane == leader)
                    atomicAdd(&hist[key], (unsigned int)__popc(grp));
            }
        }
        __syncthreads();
        unsigned int hv = hist[tid];
        unsigned int v = hv;
        #pragma unroll
        for (int o = 1; o < 32; o <<= 1) {
            unsigned int t = __shfl_up_sync(0xFFFFFFFFu, v, o);
            if (lane >= o) v += t;
        }
        if (lane == 31) wsum[wp] = v;
        __syncthreads();
        if (tid < 8) {
            unsigned int w = wsum[tid];
            #pragma unroll
            for (int o = 1; o < 8; o <<= 1) {
                unsigned int t = __shfl_up_sync(0xFFu, w, o);
                if (tid >= o) w += t;
            }
            wsum[tid] = w;
        }
        __syncthreads();
        unsigned int incl = v + (wp ? wsum[wp - 1] : 0u);
        unsigned int below = incl - hv;
        if ((unsigned)r >= below && (unsigned)r < incl) {
            s_sel = tid;
            s_r = r - (int)below;
        }
        __syncthreads();
        prefix |= ((unsigned int)s_sel) << shift;
        r = s_r;
        __syncthreads();
    }

    // v[k] = prefix; find v[k+1]: count equals + min strictly-greater
    __shared__ unsigned int s_eq, s_mg;
    if (tid == 0) { s_eq = 0u; s_mg = 0xFFFFFFFFu; }
    __syncthreads();
    unsigned int leq = 0, lmg = 0xFFFFFFFFu;
    #pragma unroll
    for (int e = 0; e < 9; e++) {
        unsigned int u = vals[e];
        if (u == prefix) leq++;
        else if (u > prefix && u < lmg) lmg = u;
    }
    if (leq) atomicAdd(&s_eq, leq);
    atomicMin(&s_mg, lmg);
    __syncthreads();
    if (tid == 0) {
        float vk = __uint_as_float(prefix);
        int lastEqRank = (k - r) + (int)s_eq - 1;
        float vk1 = (lastEqRank >= k + 1) ? vk : __uint_as_float(s_mg);
        g_thr[row] = vk * (1.0f - frac) + vk1 * frac;
    }
}

// ---------------------------------------------------------------------------
// Kernel 3: mask + IDWT + transpose. Lane = channel; each thread loads a
// 15-wide register window of lo/hi (mask applied at smem fill) and computes
// 16 consecutive outputs. 30 LDS for 256 FMA. Output writes coalesce over c.
// ---------------------------------------------------------------------------
__global__ __launch_bounds__(256) void k_idwt(float* __restrict__ out) {
    int o0 = blockIdx.x * 128;
    int c0 = blockIdx.y * 32;
    int b  = blockIdx.z;
    __shared__ float sha[32][73], shd[32][73];
    int tid = threadIdx.x, lane = tid & 31, wp = tid >> 5;
    int p0 = o0 >> 1;

    for (int cc = wp; cc < 32; cc += 8) {
        int row = b * CC + c0 + cc;
        size_t roff = (size_t)row * PITCH;
        float tv = g_thr[row];
        for (int pp = lane; pp < 71; pp += 32) {
            int p = p0 + pp;
            sha[cc][pp] = g_lo[roff + p];
            float cd = g_hi[roff + p];
            shd[cc][pp] = (cd * cd > tv) ? cd : 0.f;
        }
    }
    __syncthreads();

    // register windows: outputs oo = wp*16 .. wp*16+15, need pp in [wp*8, wp*8+14]
    float ra[15], rd[15];
    #pragma unroll
    for (int j = 0; j < 15; j++) {
        ra[j] = sha[lane][wp * 8 + j];
        rd[j] = shd[lane][wp * 8 + j];
    }

    float* ob = out + ((size_t)(b * TT) + o0 + wp * 16) * CC + c0 + lane;
    #pragma unroll
    for (int s = 0; s < 16; s++) {
        int base = s >> 1;
        float acc = 0.f;
        if (s & 1) {
            #pragma unroll
            for (int m = 0; m < 8; m++)
                acc = fmaf(ra[base + m], cRLO[15 - 2 * m],
                      fmaf(rd[base + m], cRHI[15 - 2 * m], acc));
        } else {
            #pragma unroll
            for (int m = 0; m < 8; m++)
                acc = fmaf(ra[base + m], cRLO[14 - 2 * m],
                      fmaf(rd[base + m], cRHI[14 - 2 * m], acc));
        }
        ob[(size_t)s * CC] = acc;
    }
}

extern "C" void kernel_launch(void* const* d_in, const int* in_sizes, int n_in,
                              void* d_out, int out_size) {
    const float* x  = (const float*)d_in[0];
    const float* qp = (const float*)d_in[1];
    float* out = (float*)d_out;

    dim3 g1((WW + 63) / 64, CC / 32, BB);
    k_dwt<<<g1, 256>>>(x);

    k_quant<<<NROWS, 256>>>(qp);

    dim3 g3(TT / 128, CC / 32, BB);
    k_idwt<<<g3, 256>>>(out);
}

// round 3
// speedup vs baseline: 3.2704x; 3.2704x over previous
#include <cuda_runtime.h>
#include <math.h>

#define TT 4096
#define CC 512
#define BB 32
#define WW 2055          // DWT output length
#define PITCH 2056
#define NROWS (BB*CC)    // 16384

__constant__ float cDLO[16] = {
 -0.00011747678400228192f, 0.0006754494059985568f, -0.0003917403729959771f, -0.00487035299301066f,
  0.008746094047015655f,   0.013981027917015516f,  -0.04408825393106472f,   -0.01736930100202211f,
  0.128747426620186f,      0.00047248457399797254f,-0.2840155429624281f,    -0.015829105256023893f,
  0.5853546836548691f,     0.6756307362980128f,     0.3128715909144659f,     0.05441584224308161f };
__constant__ float cDHI[16] = {
 -0.05441584224308161f,    0.3128715909144659f,    -0.6756307362980128f,     0.5853546836548691f,
  0.015829105256023893f,  -0.2840155429624281f,    -0.00047248457399797254f, 0.128747426620186f,
  0.01736930100202211f,   -0.04408825393106472f,   -0.013981027917015516f,   0.008746094047015655f,
  0.00487035299301066f,   -0.0003917403729959771f, -0.0006754494059985568f, -0.00011747678400228192f };
__constant__ float cRLO[16] = {
  0.05441584224308161f,    0.3128715909144659f,     0.6756307362980128f,     0.5853546836548691f,
 -0.015829105256023893f,  -0.2840155429624281f,     0.00047248457399797254f, 0.128747426620186f,
 -0.01736930100202211f,   -0.04408825393106472f,    0.013981027917015516f,   0.008746094047015655f,
 -0.00487035299301066f,   -0.0003917403729959771f,  0.0006754494059985568f, -0.00011747678400228192f };
__constant__ float cRHI[16] = {
 -0.00011747678400228192f,-0.0006754494059985568f, -0.0003917403729959771f,  0.00487035299301066f,
  0.008746094047015655f,  -0.013981027917015516f,  -0.04408825393106472f,    0.01736930100202211f,
  0.128747426620186f,     -0.00047248457399797254f,-0.2840155429624281f,     0.015829105256023893f,
  0.5853546836548691f,    -0.6756307362980128f,     0.3128715909144659f,    -0.05441584224308161f };

__device__ float g_lo[(size_t)NROWS * PITCH];
__device__ float g_hi[(size_t)NROWS * PITCH];
__device__ float g_thr[NROWS];

// ---------------------------------------------------------------------------
// Kernel 1: DWT. Lane = channel; 30-wide register window -> 8 output pairs.
// (R2 version, measured 96us)
// ---------------------------------------------------------------------------
__global__ __launch_bounds__(256) void k_dwt(const float* __restrict__ x) {
    int i0 = blockIdx.x * 64;
    int c0 = blockIdx.y * 32;
    int b  = blockIdx.z;
    int tid = threadIdx.x, lane = tid & 31, wp = tid >> 5;

    __shared__ float sOut[2][64][33];     // [band][i_local][channel]

    int iw0 = i0 + wp * 8;
    int p0w = 2 * iw0 - 14;               // window covers p0w .. p0w+29
    const float* xb = x + (size_t)b * TT * CC + (c0 + lane);

    float xw[30];
    if (p0w >= 0 && p0w + 29 < TT) {
        #pragma unroll
        for (int m = 0; m < 30; m++)
            xw[m] = xb[(size_t)(p0w + m) * CC];
    } else {
        #pragma unroll
        for (int m = 0; m < 30; m++) {
            int p = p0w + m;
            int t = (p < 0) ? (-1 - p) : ((p >= TT) ? (2 * TT - 1 - p) : p);
            xw[m] = xb[(size_t)t * CC];
        }
    }

    #pragma unroll
    for (int s = 0; s < 8; s++) {
        float alo = 0.f, ahi = 0.f;
        #pragma unroll
        for (int d = 0; d < 16; d++) {
            float v = xw[2 * s + 15 - d];
            alo = fmaf(v, cDLO[d], alo);
            ahi = fmaf(v, cDHI[d], ahi);
        }
        sOut[0][wp * 8 + s][lane] = alo;
        sOut[1][wp * 8 + s][lane] = ahi;
    }
    __syncthreads();

    #pragma unroll
    for (int r = 0; r < 4; r++) {
        int cc = wp * 4 + r;
        size_t rowoff = (size_t)(b * CC + c0 + cc) * PITCH;
        #pragma unroll
        for (int half = 0; half < 2; half++) {
            int il = lane + half * 32;
            int i = i0 + il;
            if (i < WW) {
                g_lo[rowoff + i] = sOut[0][il][cc];
                g_hi[rowoff + i] = sOut[1][il][cc];
            }
        }
    }
}

// ---------------------------------------------------------------------------
// Kernel 2: exact per-row quantile, 8-bit radix select on float bits.
// Per-warp privatized histograms (no inter-warp atomic contention, no
// __match_any_sync) + shfl warp scan. Sentinel 0xFFFFFFFF pads ragged tail
// (lands in bin 255 of pass 1; never selected since all real squares have
// top byte <= 0x42 and rank k < #real values).
// ---------------------------------------------------------------------------
__global__ __launch_bounds__(256) void k_quant(const float* __restrict__ qp) {
    int row = blockIdx.x;
    const float* h = g_hi + (size_t)row * PITCH;
    int tid = threadIdx.x, lane = tid & 31, wp = tid >> 5;

    unsigned int vals[9];
    #pragma unroll
    for (int e = 0; e < 9; e++) {
        int idx = tid + e * 256;
        if (idx < WW) { float v = h[idx]; vals[e] = __float_as_uint(v * v); }
        else vals[e] = 0xFFFFFFFFu;
    }

    float q = qp[0];
    float pos = q * (float)(WW - 1);
    int k = (int)floorf(pos);
    if (k < 0) k = 0;
    if (k > WW - 2) k = WW - 2;
    float frac = pos - (float)k;

    __shared__ unsigned int hist[8][256];   // per-warp privatized
    __shared__ unsigned int wsum[8];
    __shared__ int s_sel, s_r;

    unsigned int prefix = 0;
    int r = k;
    for (int shift = 24; shift >= 0; shift -= 8) {
        #pragma unroll
        for (int j = 0; j < 8; j++) hist[j][tid] = 0;
        __syncthreads();
        unsigned int maskhi = (shift == 24) ? 0u : (0xFFFFFFFFu << (shift + 8));
        #pragma unroll
        for (int e = 0; e < 9; e++) {
            unsigned int u = vals[e];
            if ((u & maskhi) == prefix)
                atomicAdd(&hist[wp][(u >> shift) & 255u], 1u);
        }
        __syncthreads();
        unsigned int hv = hist[0][tid] + hist[1][tid] + hist[2][tid] + hist[3][tid]
                        + hist[4][tid] + hist[5][tid] + hist[6][tid] + hist[7][tid];
        unsigned int v = hv;
        #pragma unroll
        for (int o = 1; o < 32; o <<= 1) {
            unsigned int t = __shfl_up_sync(0xFFFFFFFFu, v, o);
            if (lane >= o) v += t;
        }
        if (lane == 31) wsum[wp] = v;
        __syncthreads();
        if (tid < 8) {
            unsigned int w = wsum[tid];
            #pragma unroll
            for (int o = 1; o < 8; o <<= 1) {
                unsigned int t = __shfl_up_sync(0xFFu, w, o);
                if (tid >= o) w += t;
            }
            wsum[tid] = w;
        }
        __syncthreads();
        unsigned int incl = v + (wp ? wsum[wp - 1] : 0u);
        unsigned int below = incl - hv;
        if ((unsigned)r >= below && (unsigned)r < incl) {
            s_sel = tid;
            s_r = r - (int)below;
        }
        __syncthreads();
        prefix |= ((unsigned int)s_sel) << shift;
        r = s_r;
        __syncthreads();
    }

    // v[k] = prefix; v[k+1]: count equals + min strictly-greater
    __shared__ unsigned int s_eq, s_mg;
    if (tid == 0) { s_eq = 0u; s_mg = 0xFFFFFFFFu; }
    __syncthreads();
    unsigned int leq = 0, lmg = 0xFFFFFFFFu;
    #pragma unroll
    for (int e = 0; e < 9; e++) {
        unsigned int u = vals[e];
        if (u == prefix) leq++;
        else if (u > prefix && u < lmg) lmg = u;
    }
    if (leq) atomicAdd(&s_eq, leq);
    atomicMin(&s_mg, lmg);
    __syncthreads();
    if (tid == 0) {
        float vk = __uint_as_float(prefix);
        int lastEqRank = (k - r) + (int)s_eq - 1;
        float vk1 = (lastEqRank >= k + 1) ? vk : __uint_as_float(s_mg);
        g_thr[row] = vk * (1.0f - frac) + vk1 * frac;
    }
}

// ---------------------------------------------------------------------------
// Kernel 3: mask + IDWT + transpose. Register windows: 30 LDS -> 256 FMA,
// coalesced output writes over c. (R2 version)
// ---------------------------------------------------------------------------
__global__ __launch_bounds__(256) void k_idwt(float* __restrict__ out) {
    int o0 = blockIdx.x * 128;
    int c0 = blockIdx.y * 32;
    int b  = blockIdx.z;
    __shared__ float sha[32][73], shd[32][73];
    int tid = threadIdx.x, lane = tid & 31, wp = tid >> 5;
    int p0 = o0 >> 1;

    for (int cc = wp; cc < 32; cc += 8) {
        int row = b * CC + c0 + cc;
        size_t roff = (size_t)row * PITCH;
        float tv = g_thr[row];
        for (int pp = lane; pp < 71; pp += 32) {
            int p = p0 + pp;
            sha[cc][pp] = g_lo[roff + p];
            float cd = g_hi[roff + p];
            shd[cc][pp] = (cd * cd > tv) ? cd : 0.f;
        }
    }
    __syncthreads();

    float ra[15], rd[15];
    #pragma unroll
    for (int j = 0; j < 15; j++) {
        ra[j] = sha[lane][wp * 8 + j];
        rd[j] = shd[lane][wp * 8 + j];
    }

    float* ob = out + ((size_t)(b * TT) + o0 + wp * 16) * CC + c0 + lane;
    #pragma unroll
    for (int s = 0; s < 16; s++) {
        int base = s >> 1;
        float acc = 0.f;
        if (s & 1) {
            #pragma unroll
            for (int m = 0; m < 8; m++)
                acc = fmaf(ra[base + m], cRLO[15 - 2 * m],
                      fmaf(rd[base + m], cRHI[15 - 2 * m], acc));
        } else {
            #pragma unroll
            for (int m = 0; m < 8; m++)
                acc = fmaf(ra[base + m], cRLO[14 - 2 * m],
                      fmaf(rd[base + m], cRHI[14 - 2 * m], acc));
        }
        ob[(size_t)s * CC] = acc;
    }
}

extern "C" void kernel_launch(void* const* d_in, const int* in_sizes, int n_in,
                              void* d_out, int out_size) {
    const float* x  = (const float*)d_in[0];
    const float* qp = (const float*)d_in[1];
    float* out = (float*)d_out;

    dim3 g1((WW + 63) / 64, CC / 32, BB);
    k_dwt<<<g1, 256>>>(x);

    k_quant<<<NROWS, 256>>>(qp);

    dim3 g3(TT / 128, CC / 32, BB);
    k_idwt<<<g3, 256>>>(out);
}

// round 4
// speedup vs baseline: 3.3829x; 1.0344x over previous
#include <cuda_runtime.h>
#include <math.h>

#define TT 4096
#define CC 512
#define BB 32
#define WW 2055          // DWT output length
#define PITCH 2056
#define NROWS (BB*CC)    // 16384

__constant__ float cDLO[16] = {
 -0.00011747678400228192f, 0.0006754494059985568f, -0.0003917403729959771f, -0.00487035299301066f,
  0.008746094047015655f,   0.013981027917015516f,  -0.04408825393106472f,   -0.01736930100202211f,
  0.128747426620186f,      0.00047248457399797254f,-0.2840155429624281f,    -0.015829105256023893f,
  0.5853546836548691f,     0.6756307362980128f,     0.3128715909144659f,     0.05441584224308161f };
__constant__ float cDHI[16] = {
 -0.05441584224308161f,    0.3128715909144659f,    -0.6756307362980128f,     0.5853546836548691f,
  0.015829105256023893f,  -0.2840155429624281f,    -0.00047248457399797254f, 0.128747426620186f,
  0.01736930100202211f,   -0.04408825393106472f,   -0.013981027917015516f,   0.008746094047015655f,
  0.00487035299301066f,   -0.0003917403729959771f, -0.0006754494059985568f, -0.00011747678400228192f };
__constant__ float cRLO[16] = {
  0.05441584224308161f,    0.3128715909144659f,     0.6756307362980128f,     0.5853546836548691f,
 -0.015829105256023893f,  -0.2840155429624281f,     0.00047248457399797254f, 0.128747426620186f,
 -0.01736930100202211f,   -0.04408825393106472f,    0.013981027917015516f,   0.008746094047015655f,
 -0.00487035299301066f,   -0.0003917403729959771f,  0.0006754494059985568f, -0.00011747678400228192f };
__constant__ float cRHI[16] = {
 -0.00011747678400228192f,-0.0006754494059985568f, -0.0003917403729959771f,  0.00487035299301066f,
  0.008746094047015655f,  -0.013981027917015516f,  -0.04408825393106472f,    0.01736930100202211f,
  0.128747426620186f,     -0.00047248457399797254f,-0.2840155429624281f,     0.015829105256023893f,
  0.5853546836548691f,    -0.6756307362980128f,     0.3128715909144659f,    -0.05441584224308161f };

// lo: c-major [b][i][c] (only dwt writes / idwt reads it -> pick friendly layout)
__device__ float g_lo[(size_t)BB * PITCH * CC];
// hi: row-major [b*C + c][i] (quantile needs row-contiguous access)
__device__ float g_hi[(size_t)NROWS * PITCH];
__device__ float g_thr[NROWS];

// ---------------------------------------------------------------------------
// Kernel 1: DWT. Lane = channel; 30-wide register window -> 8 output pairs.
// lo written directly (c-major, coalesced). hi staged in smem for row-major
// coalesced writes.
// ---------------------------------------------------------------------------
__global__ __launch_bounds__(256) void k_dwt(const float* __restrict__ x) {
    int i0 = blockIdx.x * 64;
    int c0 = blockIdx.y * 32;
    int b  = blockIdx.z;
    int tid = threadIdx.x, lane = tid & 31, wp = tid >> 5;

    __shared__ float sHi[64][33];         // [i_local][channel]

    int iw0 = i0 + wp * 8;
    int p0w = 2 * iw0 - 14;               // window covers p0w .. p0w+29
    const float* xb = x + (size_t)b * TT * CC + (c0 + lane);

    float xw[30];
    if (p0w >= 0 && p0w + 29 < TT) {
        #pragma unroll
        for (int m = 0; m < 30; m++)
            xw[m] = __ldcs(&xb[(size_t)(p0w + m) * CC]);
    } else {
        #pragma unroll
        for (int m = 0; m < 30; m++) {
            int p = p0w + m;
            int t = (p < 0) ? (-1 - p) : ((p >= TT) ? (2 * TT - 1 - p) : p);
            xw[m] = __ldcs(&xb[(size_t)t * CC]);
        }
    }

    float* lob = g_lo + ((size_t)b * PITCH) * CC + c0 + lane;

    #pragma unroll
    for (int s = 0; s < 8; s++) {
        float alo = 0.f, ahi = 0.f;
        #pragma unroll
        for (int d = 0; d < 16; d++) {
            float v = xw[2 * s + 15 - d];
            alo = fmaf(v, cDLO[d], alo);
            ahi = fmaf(v, cDHI[d], ahi);
        }
        int i = iw0 + s;
        if (i < WW) lob[(size_t)i * CC] = alo;     // direct coalesced (lane=c)
        sHi[wp * 8 + s][lane] = ahi;
    }
    __syncthreads();

    // hi: coalesced row-major writes, 8 warps x 4 channels, lanes over i
    #pragma unroll
    for (int r = 0; r < 4; r++) {
        int cc = wp * 4 + r;
        size_t rowoff = (size_t)(b * CC + c0 + cc) * PITCH;
        #pragma unroll
        for (int half = 0; half < 2; half++) {
            int il = lane + half * 32;
            int i = i0 + il;
            if (i < WW) g_hi[rowoff + i] = sHi[il][cc];
        }
    }
}

// ---------------------------------------------------------------------------
// Kernel 2: exact per-row quantile, 8-bit radix select on float bits.
// Per-warp privatized histograms + shfl warp scan. (R3 version, proven)
// ---------------------------------------------------------------------------
__global__ __launch_bounds__(256) void k_quant(const float* __restrict__ qp) {
    int row = blockIdx.x;
    const float* h = g_hi + (size_t)row * PITCH;
    int tid = threadIdx.x, lane = tid & 31, wp = tid >> 5;

    unsigned int vals[9];
    #pragma unroll
    for (int e = 0; e < 9; e++) {
        int idx = tid + e * 256;
        if (idx < WW) { float v = h[idx]; vals[e] = __float_as_uint(v * v); }
        else vals[e] = 0xFFFFFFFFu;
    }

    float q = qp[0];
    float pos = q * (float)(WW - 1);
    int k = (int)floorf(pos);
    if (k < 0) k = 0;
    if (k > WW - 2) k = WW - 2;
    float frac = pos - (float)k;

    __shared__ unsigned int hist[8][256];
    __shared__ unsigned int wsum[8];
    __shared__ int s_sel, s_r;

    unsigned int prefix = 0;
    int r = k;
    for (int shift = 24; shift >= 0; shift -= 8) {
        #pragma unroll
        for (int j = 0; j < 8; j++) hist[j][tid] = 0;
        __syncthreads();
        unsigned int maskhi = (shift == 24) ? 0u : (0xFFFFFFFFu << (shift + 8));
        #pragma unroll
        for (int e = 0; e < 9; e++) {
            unsigned int u = vals[e];
            if ((u & maskhi) == prefix)
                atomicAdd(&hist[wp][(u >> shift) & 255u], 1u);
        }
        __syncthreads();
        unsigned int hv = hist[0][tid] + hist[1][tid] + hist[2][tid] + hist[3][tid]
                        + hist[4][tid] + hist[5][tid] + hist[6][tid] + hist[7][tid];
        unsigned int v = hv;
        #pragma unroll
        for (int o = 1; o < 32; o <<= 1) {
            unsigned int t = __shfl_up_sync(0xFFFFFFFFu, v, o);
            if (lane >= o) v += t;
        }
        if (lane == 31) wsum[wp] = v;
        __syncthreads();
        if (tid < 8) {
            unsigned int w = wsum[tid];
            #pragma unroll
            for (int o = 1; o < 8; o <<= 1) {
                unsigned int t = __shfl_up_sync(0xFFu, w, o);
                if (tid >= o) w += t;
            }
            wsum[tid] = w;
        }
        __syncthreads();
        unsigned int incl = v + (wp ? wsum[wp - 1] : 0u);
        unsigned int below = incl - hv;
        if ((unsigned)r >= below && (unsigned)r < incl) {
            s_sel = tid;
            s_r = r - (int)below;
        }
        __syncthreads();
        prefix |= ((unsigned int)s_sel) << shift;
        r = s_r;
        __syncthreads();
    }

    __shared__ unsigned int s_eq, s_mg;
    if (tid == 0) { s_eq = 0u; s_mg = 0xFFFFFFFFu; }
    __syncthreads();
    unsigned int leq = 0, lmg = 0xFFFFFFFFu;
    #pragma unroll
    for (int e = 0; e < 9; e++) {
        unsigned int u = vals[e];
        if (u == prefix) leq++;
        else if (u > prefix && u < lmg) lmg = u;
    }
    if (leq) atomicAdd(&s_eq, leq);
    atomicMin(&s_mg, lmg);
    __syncthreads();
    if (tid == 0) {
        float vk = __uint_as_float(prefix);
        int lastEqRank = (k - r) + (int)s_eq - 1;
        float vk1 = (lastEqRank >= k + 1) ? vk : __uint_as_float(s_mg);
        g_thr[row] = vk * (1.0f - frac) + vk1 * frac;
    }
}

// ---------------------------------------------------------------------------
// Kernel 3: mask + IDWT + transpose. lo read directly from c-major layout
// (coalesced register-window loads); hi staged via smem (mask applied).
// ---------------------------------------------------------------------------
__global__ __launch_bounds__(256) void k_idwt(float* __restrict__ out) {
    int o0 = blockIdx.x * 128;
    int c0 = blockIdx.y * 32;
    int b  = blockIdx.z;
    __shared__ float shd[32][73];
    int tid = threadIdx.x, lane = tid & 31, wp = tid >> 5;
    int p0 = o0 >> 1;

    // stage hi (masked) row-major -> smem
    for (int cc = wp; cc < 32; cc += 8) {
        int row = b * CC + c0 + cc;
        size_t roff = (size_t)row * PITCH;
        float tv = g_thr[row];
        for (int pp = lane; pp < 71; pp += 32) {
            float cd = g_hi[roff + p0 + pp];
            shd[cc][pp] = (cd * cd > tv) ? cd : 0.f;
        }
    }

    // lo register window: direct coalesced global loads (lane = channel)
    int pw0 = p0 + wp * 8;
    const float* lob = g_lo + ((size_t)b * PITCH + pw0) * CC + c0 + lane;
    float ra[15];
    #pragma unroll
    for (int j = 0; j < 15; j++)
        ra[j] = lob[(size_t)j * CC];

    __syncthreads();

    float rd[15];
    #pragma unroll
    for (int j = 0; j < 15; j++)
        rd[j] = shd[lane][wp * 8 + j];

    float* ob = out + ((size_t)(b * TT) + o0 + wp * 16) * CC + c0 + lane;
    #pragma unroll
    for (int s = 0; s < 16; s++) {
        int base = s >> 1;
        float acc = 0.f;
        if (s & 1) {
            #pragma unroll
            for (int m = 0; m < 8; m++)
                acc = fmaf(ra[base + m], cRLO[15 - 2 * m],
                      fmaf(rd[base + m], cRHI[15 - 2 * m], acc));
        } else {
            #pragma unroll
            for (int m = 0; m < 8; m++)
                acc = fmaf(ra[base + m], cRLO[14 - 2 * m],
                      fmaf(rd[base + m], cRHI[14 - 2 * m], acc));
        }
        __stcs(&ob[(size_t)s * CC], acc);
    }
}

extern "C" void kernel_launch(void* const* d_in, const int* in_sizes, int n_in,
                              void* d_out, int out_size) {
    const float* x  = (const float*)d_in[0];
    const float* qp = (const float*)d_in[1];
    float* out = (float*)d_out;

    dim3 g1((WW + 63) / 64, CC / 32, BB);
    k_dwt<<<g1, 256>>>(x);

    k_quant<<<NROWS, 256>>>(qp);

    dim3 g3(TT / 128, CC / 32, BB);
    k_idwt<<<g3, 256>>>(out);
}

// round 5
// speedup vs baseline: 3.4849x; 1.0302x over previous
#include <cuda_runtime.h>
#include <math.h>

#define TT 4096
#define CC 512
#define BB 32
#define WW 2055          // DWT output length
#define PITCH 2056
#define NROWS (BB*CC)    // 16384

__constant__ float cDLO[16] = {
 -0.00011747678400228192f, 0.0006754494059985568f, -0.0003917403729959771f, -0.00487035299301066f,
  0.008746094047015655f,   0.013981027917015516f,  -0.04408825393106472f,   -0.01736930100202211f,
  0.128747426620186f,      0.00047248457399797254f,-0.2840155429624281f,    -0.015829105256023893f,
  0.5853546836548691f,     0.6756307362980128f,     0.3128715909144659f,     0.05441584224308161f };
__constant__ float cDHI[16] = {
 -0.05441584224308161f,    0.3128715909144659f,    -0.6756307362980128f,     0.5853546836548691f,
  0.015829105256023893f,  -0.2840155429624281f,    -0.00047248457399797254f, 0.128747426620186f,
  0.01736930100202211f,   -0.04408825393106472f,   -0.013981027917015516f,   0.008746094047015655f,
  0.00487035299301066f,   -0.0003917403729959771f, -0.0006754494059985568f, -0.00011747678400228192f };
__constant__ float cRLO[16] = {
  0.05441584224308161f,    0.3128715909144659f,     0.6756307362980128f,     0.5853546836548691f,
 -0.015829105256023893f,  -0.2840155429624281f,     0.00047248457399797254f, 0.128747426620186f,
 -0.01736930100202211f,   -0.04408825393106472f,    0.013981027917015516f,   0.008746094047015655f,
 -0.00487035299301066f,   -0.0003917403729959771f,  0.0006754494059985568f, -0.00011747678400228192f };
__constant__ float cRHI[16] = {
 -0.00011747678400228192f,-0.0006754494059985568f, -0.0003917403729959771f,  0.00487035299301066f,
  0.008746094047015655f,  -0.013981027917015516f,  -0.04408825393106472f,    0.01736930100202211f,
  0.128747426620186f,     -0.00047248457399797254f,-0.2840155429624281f,     0.015829105256023893f,
  0.5853546836548691f,    -0.6756307362980128f,     0.3128715909144659f,    -0.05441584224308161f };

// lo: c-major [b][i][c]; hi: row-major [b*C+c][i] (quantile reads rows)
__device__ float g_lo[(size_t)BB * PITCH * CC];
__device__ float g_hi[(size_t)NROWS * PITCH];
__device__ float g_thr[NROWS];
__device__ int   g_dummy;

// Dummy kernel: shifts ncu's fixed capture slot so a non-dwt kernel gets
// profiled. Deterministic, graph-safe, ~2us.
__global__ void k_nop() { g_dummy = 1; }

// ---------------------------------------------------------------------------
// Kernel 1: DWT. Lane = channel; 30-wide register window -> 8 output pairs.
// x and lo are single-use streams (evict-first); hi left evict-normal so it
// stays L2-resident for k_quant.
// ---------------------------------------------------------------------------
__global__ __launch_bounds__(256) void k_dwt(const float* __restrict__ x) {
    int i0 = blockIdx.x * 64;
    int c0 = blockIdx.y * 32;
    int b  = blockIdx.z;
    int tid = threadIdx.x, lane = tid & 31, wp = tid >> 5;

    __shared__ float sHi[64][33];         // [i_local][channel]

    int iw0 = i0 + wp * 8;
    int p0w = 2 * iw0 - 14;               // window covers p0w .. p0w+29
    const float* xb = x + (size_t)b * TT * CC + (c0 + lane);

    float xw[30];
    if (p0w >= 0 && p0w + 29 < TT) {
        #pragma unroll
        for (int m = 0; m < 30; m++)
            xw[m] = __ldcs(&xb[(size_t)(p0w + m) * CC]);
    } else {
        #pragma unroll
        for (int m = 0; m < 30; m++) {
            int p = p0w + m;
            int t = (p < 0) ? (-1 - p) : ((p >= TT) ? (2 * TT - 1 - p) : p);
            xw[m] = __ldcs(&xb[(size_t)t * CC]);
        }
    }

    float* lob = g_lo + ((size_t)b * PITCH) * CC + c0 + lane;

    #pragma unroll
    for (int s = 0; s < 8; s++) {
        float alo = 0.f, ahi = 0.f;
        #pragma unroll
        for (int d = 0; d < 16; d++) {
            float v = xw[2 * s + 15 - d];
            alo = fmaf(v, cDLO[d], alo);
            ahi = fmaf(v, cDHI[d], ahi);
        }
        int i = iw0 + s;
        if (i < WW) __stcs(&lob[(size_t)i * CC], alo);   // streamed
        sHi[wp * 8 + s][lane] = ahi;
    }
    __syncthreads();

    #pragma unroll
    for (int r = 0; r < 4; r++) {
        int cc = wp * 4 + r;
        size_t rowoff = (size_t)(b * CC + c0 + cc) * PITCH;
        #pragma unroll
        for (int half = 0; half < 2; half++) {
            int il = lane + half * 32;
            int i = i0 + il;
            if (i < WW) g_hi[rowoff + i] = sHi[il][cc];   // evict-normal
        }
    }
}

// ---------------------------------------------------------------------------
// Kernel 2: exact per-row quantile, 8-bit radix select on float bits.
// Rows processed in REVERSE so the first rows read are the ones k_dwt wrote
// last (still L2-resident). hi reads evict-normal (idwt re-reads them).
// ---------------------------------------------------------------------------
__global__ __launch_bounds__(256) void k_quant(const float* __restrict__ qp) {
    int row = NROWS - 1 - blockIdx.x;
    const float* h = g_hi + (size_t)row * PITCH;
    int tid = threadIdx.x, lane = tid & 31, wp = tid >> 5;

    unsigned int vals[9];
    #pragma unroll
    for (int e = 0; e < 9; e++) {
        int idx = tid + e * 256;
        if (idx < WW) { float v = h[idx]; vals[e] = __float_as_uint(v * v); }
        else vals[e] = 0xFFFFFFFFu;
    }

    float q = qp[0];
    float pos = q * (float)(WW - 1);
    int k = (int)floorf(pos);
    if (k < 0) k = 0;
    if (k > WW - 2) k = WW - 2;
    float frac = pos - (float)k;

    __shared__ unsigned int hist[8][256];
    __shared__ unsigned int wsum[8];
    __shared__ int s_sel, s_r;

    unsigned int prefix = 0;
    int r = k;
    for (int shift = 24; shift >= 0; shift -= 8) {
        #pragma unroll
        for (int j = 0; j < 8; j++) hist[j][tid] = 0;
        __syncthreads();
        unsigned int maskhi = (shift == 24) ? 0u : (0xFFFFFFFFu << (shift + 8));
        #pragma unroll
        for (int e = 0; e < 9; e++) {
            unsigned int u = vals[e];
            if ((u & maskhi) == prefix)
                atomicAdd(&hist[wp][(u >> shift) & 255u], 1u);
        }
        __syncthreads();
        unsigned int hv = hist[0][tid] + hist[1][tid] + hist[2][tid] + hist[3][tid]
                        + hist[4][tid] + hist[5][tid] + hist[6][tid] + hist[7][tid];
        unsigned int v = hv;
        #pragma unroll
        for (int o = 1; o < 32; o <<= 1) {
            unsigned int t = __shfl_up_sync(0xFFFFFFFFu, v, o);
            if (lane >= o) v += t;
        }
        if (lane == 31) wsum[wp] = v;
        __syncthreads();
        if (tid < 8) {
            unsigned int w = wsum[tid];
            #pragma unroll
            for (int o = 1; o < 8; o <<= 1) {
                unsigned int t = __shfl_up_sync(0xFFu, w, o);
                if (tid >= o) w += t;
            }
            wsum[tid] = w;
        }
        __syncthreads();
        unsigned int incl = v + (wp ? wsum[wp - 1] : 0u);
        unsigned int below = incl - hv;
        if ((unsigned)r >= below && (unsigned)r < incl) {
            s_sel = tid;
            s_r = r - (int)below;
        }
        __syncthreads();
        prefix |= ((unsigned int)s_sel) << shift;
        r = s_r;
        __syncthreads();
    }

    __shared__ unsigned int s_eq, s_mg;
    if (tid == 0) { s_eq = 0u; s_mg = 0xFFFFFFFFu; }
    __syncthreads();
    unsigned int leq = 0, lmg = 0xFFFFFFFFu;
    #pragma unroll
    for (int e = 0; e < 9; e++) {
        unsigned int u = vals[e];
        if (u == prefix) leq++;
        else if (u > prefix && u < lmg) lmg = u;
    }
    if (leq) atomicAdd(&s_eq, leq);
    atomicMin(&s_mg, lmg);
    __syncthreads();
    if (tid == 0) {
        float vk = __uint_as_float(prefix);
        int lastEqRank = (k - r) + (int)s_eq - 1;
        float vk1 = (lastEqRank >= k + 1) ? vk : __uint_as_float(s_mg);
        g_thr[row] = vk * (1.0f - frac) + vk1 * frac;
    }
}

// ---------------------------------------------------------------------------
// Kernel 3: mask + IDWT + transpose. lo from c-major layout (coalesced,
// streamed); hi (last use) via __ldcs; out streamed.
// ---------------------------------------------------------------------------
__global__ __launch_bounds__(256) void k_idwt(float* __restrict__ out) {
    int o0 = blockIdx.x * 128;
    int c0 = blockIdx.y * 32;
    int b  = blockIdx.z;
    __shared__ float shd[32][73];
    int tid = threadIdx.x, lane = tid & 31, wp = tid >> 5;
    int p0 = o0 >> 1;

    for (int cc = wp; cc < 32; cc += 8) {
        int row = b * CC + c0 + cc;
        size_t roff = (size_t)row * PITCH;
        float tv = g_thr[row];
        for (int pp = lane; pp < 71; pp += 32) {
            float cd = __ldcs(&g_hi[roff + p0 + pp]);
            shd[cc][pp] = (cd * cd > tv) ? cd : 0.f;
        }
    }

    int pw0 = p0 + wp * 8;
    const float* lob = g_lo + ((size_t)b * PITCH + pw0) * CC + c0 + lane;
    float ra[15];
    #pragma unroll
    for (int j = 0; j < 15; j++)
        ra[j] = __ldcs(&lob[(size_t)j * CC]);

    __syncthreads();

    float rd[15];
    #pragma unroll
    for (int j = 0; j < 15; j++)
        rd[j] = shd[lane][wp * 8 + j];

    float* ob = out + ((size_t)(b * TT) + o0 + wp * 16) * CC + c0 + lane;
    #pragma unroll
    for (int s = 0; s < 16; s++) {
        int base = s >> 1;
        float acc = 0.f;
        if (s & 1) {
            #pragma unroll
            for (int m = 0; m < 8; m++)
                acc = fmaf(ra[base + m], cRLO[15 - 2 * m],
                      fmaf(rd[base + m], cRHI[15 - 2 * m], acc));
        } else {
            #pragma unroll
            for (int m = 0; m < 8; m++)
                acc = fmaf(ra[base + m], cRLO[14 - 2 * m],
                      fmaf(rd[base + m], cRHI[14 - 2 * m], acc));
        }
        __stcs(&ob[(size_t)s * CC], acc);
    }
}

extern "C" void kernel_launch(void* const* d_in, const int* in_sizes, int n_in,
                              void* d_out, int out_size) {
    const float* x  = (const float*)d_in[0];
    const float* qp = (const float*)d_in[1];
    float* out = (float*)d_out;

    k_nop<<<1, 1>>>();                    // shifts ncu capture slot off k_dwt

    dim3 g1((WW + 63) / 64, CC / 32, BB);
    k_dwt<<<g1, 256>>>(x);

    k_quant<<<NROWS, 256>>>(qp);

    dim3 g3(TT / 128, CC / 32, BB);
    k_idwt<<<g3, 256>>>(out);
}

// round 7
// speedup vs baseline: 3.8239x; 1.0973x over previous
#include <cuda_runtime.h>
#include <math.h>

#define TT 4096
#define CC 512
#define BB 32
#define WW 2055          // DWT output length
#define PITCH 2056
#define NROWS (BB*CC)    // 16384

__constant__ float cDLO[16] = {
 -0.00011747678400228192f, 0.0006754494059985568f, -0.0003917403729959771f, -0.00487035299301066f,
  0.008746094047015655f,   0.013981027917015516f,  -0.04408825393106472f,   -0.01736930100202211f,
  0.128747426620186f,      0.00047248457399797254f,-0.2840155429624281f,    -0.015829105256023893f,
  0.5853546836548691f,     0.6756307362980128f,     0.3128715909144659f,     0.05441584224308161f };
__constant__ float cDHI[16] = {
 -0.05441584224308161f,    0.3128715909144659f,    -0.6756307362980128f,     0.5853546836548691f,
  0.015829105256023893f,  -0.2840155429624281f,    -0.00047248457399797254f, 0.128747426620186f,
  0.01736930100202211f,   -0.04408825393106472f,   -0.013981027917015516f,   0.008746094047015655f,
  0.00487035299301066f,   -0.0003917403729959771f, -0.0006754494059985568f, -0.00011747678400228192f };
__constant__ float cRLO[16] = {
  0.05441584224308161f,    0.3128715909144659f,     0.6756307362980128f,     0.5853546836548691f,
 -0.015829105256023893f,  -0.2840155429624281f,     0.00047248457399797254f, 0.128747426620186f,
 -0.01736930100202211f,   -0.04408825393106472f,    0.013981027917015516f,   0.008746094047015655f,
 -0.00487035299301066f,   -0.0003917403729959771f,  0.0006754494059985568f, -0.00011747678400228192f };
__constant__ float cRHI[16] = {
 -0.00011747678400228192f,-0.0006754494059985568f, -0.0003917403729959771f,  0.00487035299301066f,
  0.008746094047015655f,  -0.013981027917015516f,  -0.04408825393106472f,    0.01736930100202211f,
  0.128747426620186f,     -0.00047248457399797254f,-0.2840155429624281f,     0.015829105256023893f,
  0.5853546836548691f,    -0.6756307362980128f,     0.3128715909144659f,    -0.05441584224308161f };

// lo: c-major [b][i][c]; hi: row-major [b*C+c][i]
__device__ float g_lo[(size_t)BB * PITCH * CC];
__device__ float g_hi[(size_t)NROWS * PITCH];
__device__ float g_thr[NROWS];
__device__ int   g_dummy;

__global__ void k_nop() { g_dummy = 1; }

// ---------------------------------------------------------------------------
// Kernel 1: DWT (unchanged; measured 96us, DRAM 63%).
// ---------------------------------------------------------------------------
__global__ __launch_bounds__(256) void k_dwt(const float* __restrict__ x) {
    int i0 = blockIdx.x * 64;
    int c0 = blockIdx.y * 32;
    int b  = blockIdx.z;
    int tid = threadIdx.x, lane = tid & 31, wp = tid >> 5;

    __shared__ float sHi[64][33];

    int iw0 = i0 + wp * 8;
    int p0w = 2 * iw0 - 14;
    const float* xb = x + (size_t)b * TT * CC + (c0 + lane);

    float xw[30];
    if (p0w >= 0 && p0w + 29 < TT) {
        #pragma unroll
        for (int m = 0; m < 30; m++)
            xw[m] = __ldcs(&xb[(size_t)(p0w + m) * CC]);
    } else {
        #pragma unroll
        for (int m = 0; m < 30; m++) {
            int p = p0w + m;
            int t = (p < 0) ? (-1 - p) : ((p >= TT) ? (2 * TT - 1 - p) : p);
            xw[m] = __ldcs(&xb[(size_t)t * CC]);
        }
    }

    float* lob = g_lo + ((size_t)b * PITCH) * CC + c0 + lane;

    #pragma unroll
    for (int s = 0; s < 8; s++) {
        float alo = 0.f, ahi = 0.f;
        #pragma unroll
        for (int d = 0; d < 16; d++) {
            float v = xw[2 * s + 15 - d];
            alo = fmaf(v, cDLO[d], alo);
            ahi = fmaf(v, cDHI[d], ahi);
        }
        int i = iw0 + s;
        if (i < WW) __stcs(&lob[(size_t)i * CC], alo);
        sHi[wp * 8 + s][lane] = ahi;
    }
    __syncthreads();

    #pragma unroll
    for (int r = 0; r < 4; r++) {
        int cc = wp * 4 + r;
        size_t rowoff = (size_t)(b * CC + c0 + cc) * PITCH;
        #pragma unroll
        for (int half = 0; half < 2; half++) {
            int il = lane + half * 32;
            int i = i0 + il;
            if (i < WW) g_hi[rowoff + i] = sHi[il][cc];
        }
    }
}

// ---------------------------------------------------------------------------
// Kernel 2: per-row quantile (radix select), LDG.128 loads.
// ---------------------------------------------------------------------------
__global__ __launch_bounds__(256) void k_quant(const float* __restrict__ qp) {
    int row = NROWS - 1 - blockIdx.x;
    const float* h = g_hi + (size_t)row * PITCH;
    int tid = threadIdx.x, lane = tid & 31, wp = tid >> 5;

    unsigned int vals[9];
    {
        const float4* h4 = (const float4*)h;
        float4 a = h4[tid * 2];
        float4 bq = h4[tid * 2 + 1];
        vals[0] = __float_as_uint(a.x * a.x);
        vals[1] = __float_as_uint(a.y * a.y);
        vals[2] = __float_as_uint(a.z * a.z);
        vals[3] = __float_as_uint(a.w * a.w);
        vals[4] = __float_as_uint(bq.x * bq.x);
        vals[5] = __float_as_uint(bq.y * bq.y);
        vals[6] = __float_as_uint(bq.z * bq.z);
        vals[7] = __float_as_uint(bq.w * bq.w);
        if (tid < WW - 2048) { float v = h[2048 + tid]; vals[8] = __float_as_uint(v * v); }
        else vals[8] = 0xFFFFFFFFu;
    }

    float q = qp[0];
    float pos = q * (float)(WW - 1);
    int k = (int)floorf(pos);
    if (k < 0) k = 0;
    if (k > WW - 2) k = WW - 2;
    float frac = pos - (float)k;

    __shared__ unsigned int hist[8][256];
    __shared__ unsigned int wsum[8];
    __shared__ int s_sel, s_r;

    unsigned int prefix = 0;
    int r = k;
    for (int shift = 24; shift >= 0; shift -= 8) {
        #pragma unroll
        for (int j = 0; j < 8; j++) hist[j][tid] = 0;
        __syncthreads();
        unsigned int maskhi = (shift == 24) ? 0u : (0xFFFFFFFFu << (shift + 8));
        #pragma unroll
        for (int e = 0; e < 9; e++) {
            unsigned int u = vals[e];
            if ((u & maskhi) == prefix)
                atomicAdd(&hist[wp][(u >> shift) & 255u], 1u);
        }
        __syncthreads();
        unsigned int hv = hist[0][tid] + hist[1][tid] + hist[2][tid] + hist[3][tid]
                        + hist[4][tid] + hist[5][tid] + hist[6][tid] + hist[7][tid];
        unsigned int v = hv;
        #pragma unroll
        for (int o = 1; o < 32; o <<= 1) {
            unsigned int t = __shfl_up_sync(0xFFFFFFFFu, v, o);
            if (lane >= o) v += t;
        }
        if (lane == 31) wsum[wp] = v;
        __syncthreads();
        if (tid < 8) {
            unsigned int w = wsum[tid];
            #pragma unroll
            for (int o = 1; o < 8; o <<= 1) {
                unsigned int t = __shfl_up_sync(0xFFu, w, o);
                if (tid >= o) w += t;
            }
            wsum[tid] = w;
        }
        __syncthreads();
        unsigned int incl = v + (wp ? wsum[wp - 1] : 0u);
        unsigned int below = incl - hv;
        if ((unsigned)r >= below && (unsigned)r < incl) {
            s_sel = tid;
            s_r = r - (int)below;
        }
        __syncthreads();
        prefix |= ((unsigned int)s_sel) << shift;
        r = s_r;
        __syncthreads();
    }

    __shared__ unsigned int s_eq, s_mg;
    if (tid == 0) { s_eq = 0u; s_mg = 0xFFFFFFFFu; }
    __syncthreads();
    unsigned int leq = 0, lmg = 0xFFFFFFFFu;
    #pragma unroll
    for (int e = 0; e < 9; e++) {
        unsigned int u = vals[e];
        if (u == prefix) leq++;
        else if (u > prefix && u < lmg) lmg = u;
    }
    if (leq) atomicAdd(&s_eq, leq);
    atomicMin(&s_mg, lmg);
    __syncthreads();
    if (tid == 0) {
        float vk = __uint_as_float(prefix);
        int lastEqRank = (k - r) + (int)s_eq - 1;
        float vk1 = (lastEqRank >= k + 1) ? vk : __uint_as_float(s_mg);
        g_thr[row] = vk * (1.0f - frac) + vk1 * frac;
    }
}

// ---------------------------------------------------------------------------
// Kernel 3: mask + IDWT + transpose, float2 over channels.
// FIX vs R6: smem tile stride 65 -> 66 floats (264B, multiple of 8) so all
// float2 LDS are 8-byte aligned (65*4=260B trapped on odd rows).
// ---------------------------------------------------------------------------
__global__ __launch_bounds__(256) void k_idwt(float* __restrict__ out) {
    int o0 = blockIdx.x * 128;
    int c0 = blockIdx.y * 64;
    int b  = blockIdx.z;
    __shared__ float shd[72][66];          // [pp][channel]; EVEN stride: aligned
    int tid = threadIdx.x, lane = tid & 31, wp = tid >> 5;
    int p0 = o0 >> 1;

    // stage hi (masked): each warp handles 8 channels; row reads via LDG.64
    #pragma unroll
    for (int it = 0; it < 8; it++) {
        int cc = wp * 8 + it;
        int row = b * CC + c0 + cc;
        const float2* hrow = (const float2*)(g_hi + (size_t)row * PITCH + p0);
        float tv = g_thr[row];
        float2 v = __ldcs(&hrow[lane]);                 // pp = 2*lane, 2*lane+1
        shd[2 * lane][cc]     = (v.x * v.x > tv) ? v.x : 0.f;
        shd[2 * lane + 1][cc] = (v.y * v.y > tv) ? v.y : 0.f;
        if (lane < 4) {                                 // pp = 64..71
            float2 w = __ldcs(&hrow[32 + lane]);
            shd[64 + 2 * lane][cc]     = (w.x * w.x > tv) ? w.x : 0.f;
            shd[64 + 2 * lane + 1][cc] = (w.y * w.y > tv) ? w.y : 0.f;
        }
    }

    // lo register window: float2 coalesced loads (lane = channel pair)
    int pw0 = p0 + wp * 8;
    const float* lob = g_lo + ((size_t)b * PITCH + pw0) * CC + c0 + 2 * lane;
    float2 ra[15];
    #pragma unroll
    for (int j = 0; j < 15; j++)
        ra[j] = __ldcs((const float2*)&lob[(size_t)j * CC]);

    __syncthreads();

    float2 rd[15];
    #pragma unroll
    for (int j = 0; j < 15; j++)
        rd[j] = *(const float2*)&shd[wp * 8 + j][2 * lane];

    float* ob = out + ((size_t)(b * TT) + o0 + wp * 16) * CC + c0 + 2 * lane;
    #pragma unroll
    for (int s = 0; s < 16; s++) {
        int base = s >> 1;
        float ax = 0.f, ay = 0.f;
        if (s & 1) {
            #pragma unroll
            for (int m = 0; m < 8; m++) {
                float fl = cRLO[15 - 2 * m], fh = cRHI[15 - 2 * m];
                ax = fmaf(ra[base + m].x, fl, fmaf(rd[base + m].x, fh, ax));
                ay = fmaf(ra[base + m].y, fl, fmaf(rd[base + m].y, fh, ay));
            }
        } else {
            #pragma unroll
            for (int m = 0; m < 8; m++) {
                float fl = cRLO[14 - 2 * m], fh = cRHI[14 - 2 * m];
                ax = fmaf(ra[base + m].x, fl, fmaf(rd[base + m].x, fh, ax));
                ay = fmaf(ra[base + m].y, fl, fmaf(rd[base + m].y, fh, ay));
            }
        }
        float2 res = make_float2(ax, ay);
        __stcs((float2*)&ob[(size_t)s * CC], res);
    }
}

extern "C" void kernel_launch(void* const* d_in, const int* in_sizes, int n_in,
                              void* d_out, int out_size) {
    const float* x  = (const float*)d_in[0];
    const float* qp = (const float*)d_in[1];
    float* out = (float*)d_out;

    k_nop<<<1, 1>>>();                    // capture-slot shift (2 nops -> quant)
    k_nop<<<1, 1>>>();

    dim3 g1((WW + 63) / 64, CC / 32, BB);
    k_dwt<<<g1, 256>>>(x);

    k_quant<<<NROWS, 256>>>(qp);

    dim3 g3(TT / 128, CC / 64, BB);       // 32 x 8 x 32
    k_idwt<<<g3, 256>>>(out);
}